// round 17
// baseline (speedup 1.0000x reference)
#include <cuda_runtime.h>
#include <math.h>

// Problem constants
#define Bb 4
#define Ss 20
#define IMm 64
#define Dd 8
#define NLl 4
#define NPOS (Bb*Ss*IMm*IMm)
#define NELEM (NPOS*Dd)
#define LOG2E 1.4426950408889634f
#define QSCALE (0.5f * LOG2E)

// Scratch (no allocations allowed)
__device__ float g_xt[NELEM];
__device__ float g_bufA[NELEM];
__device__ float g_bufB[NELEM];
__device__ float g_logits[Bb];

// ---------------- packed f32x2 helpers (sm_103a) ----------------
typedef unsigned long long u64t;
__device__ __forceinline__ u64t pk2(float lo, float hi) {
    u64t r; asm("mov.b64 %0, {%1,%2};" : "=l"(r) : "f"(lo), "f"(hi)); return r;
}
__device__ __forceinline__ void up2(u64t v, float& a, float& b) {
    asm("mov.b64 {%0,%1}, %2;" : "=f"(a), "=f"(b) : "l"(v));
}
__device__ __forceinline__ u64t fma2(u64t a, u64t b, u64t c) {
    u64t d; asm("fma.rn.f32x2 %0, %1, %2, %3;" : "=l"(d) : "l"(a), "l"(b), "l"(c)); return d;
}
__device__ __forceinline__ u64t mul2(u64t a, u64t b) {
    u64t d; asm("mul.rn.f32x2 %0, %1, %2;" : "=l"(d) : "l"(a), "l"(b)); return d;
}
__device__ __forceinline__ u64t add2(u64t a, u64t b) {
    u64t d; asm("add.rn.f32x2 %0, %1, %2;" : "=l"(d) : "l"(a), "l"(b)); return d;
}
__device__ __forceinline__ float ex2f(float x) {
    float r; asm("ex2.approx.f32 %0, %1;" : "=f"(r) : "f"(x)); return r;
}

// ---------------------------------------------------------------------------
// Axial attention, L=64. 128 threads = 4 heads x 32 lanes. Each thread
// handles TWO rows (i, i+32) of its head -> K/V smem reads amortized 2x.
// Single-pass softmax in log2 domain (no max; args O(1), exp2 safe).
// ---------------------------------------------------------------------------
__global__ void __launch_bounds__(128, 4)
axial_attn64(const float* __restrict__ zin, float* __restrict__ zout,
             const float* __restrict__ Wq, const float* __restrict__ Wkv,
             const float* __restrict__ Wo, const float* __restrict__ bo,
             int inner_count, int outer_mult, int stride, int accum)
{
    __shared__ float  sWq[128];        // pre-scaled by 0.5*log2e
    __shared__ float2 sKV2[8][16];     // [d][h*4+e] = (k_w, v_w)
    __shared__ float  sWo[128];
    __shared__ float  sbo[8];
    __shared__ __align__(16) float sK[4][4][64];   // [h][e][j]
    __shared__ __align__(16) float sV[4][4][64];
    __shared__ float  sPart[4][8][64]; // [h][d][row]

    const int tid = threadIdx.x;      // 0..127
    const int h   = tid >> 5;         // head
    const int i0  = tid & 31;         // lane: rows i0 and i0+32

    sWq[tid] = Wq[tid] * QSCALE;
    {
        int d = tid >> 4, c = tid & 15;
        sKV2[d][c] = make_float2(Wkv[d * 32 + c], Wkv[d * 32 + 16 + c]);
    }
    sWo[tid] = Wo[tid];
    if (tid < 8) sbo[tid] = bo[tid];

    const int seq   = blockIdx.x;
    const int outer = seq / inner_count;
    const int rem   = seq - outer * inner_count;
    const long base = (long)outer * outer_mult + rem;

    // load my two rows
    const float* zrA = zin + (base + (long)i0 * stride) * 8;
    const float* zrB = zin + (base + (long)(i0 + 32) * stride) * 8;
    float4 aA0 = *(const float4*)zrA;
    float4 aA1 = *(const float4*)(zrA + 4);
    float4 aB0 = *(const float4*)zrB;
    float4 aB1 = *(const float4*)(zrB + 4);
    float rowA[8] = {aA0.x, aA0.y, aA0.z, aA0.w, aA1.x, aA1.y, aA1.z, aA1.w};
    float rowB[8] = {aB0.x, aB0.y, aB0.z, aB0.w, aB1.x, aB1.y, aB1.z, aB1.w};

    __syncthreads();  // weights ready

    // k,v projection (packed over (k,v)) for both rows -> shared
    const u64t* kvw = (const u64t*)&sKV2[0][0];
#pragma unroll
    for (int e = 0; e < 4; e++) {
        u64t wA = kvw[0 * 16 + h * 4 + e];
        u64t accA = mul2(pk2(rowA[0], rowA[0]), wA);
        u64t accB = mul2(pk2(rowB[0], rowB[0]), wA);
#pragma unroll
        for (int d = 1; d < 8; d++) {
            u64t w = kvw[d * 16 + h * 4 + e];
            accA = fma2(pk2(rowA[d], rowA[d]), w, accA);
            accB = fma2(pk2(rowB[d], rowB[d]), w, accB);
        }
        float kA, vA, kB, vB;
        up2(accA, kA, vA);
        up2(accB, kB, vB);
        sK[h][e][i0]      = kA;  sV[h][e][i0]      = vA;
        sK[h][e][i0 + 32] = kB;  sV[h][e][i0 + 32] = vB;
    }

    // q projection (pre-scaled) for both rows
    u64t qpA[4], qpB[4];
#pragma unroll
    for (int e = 0; e < 4; e++) {
        float sA = 0.0f, sB = 0.0f;
#pragma unroll
        for (int d = 0; d < 8; d++) {
            float w = sWq[d * 16 + h * 4 + e];
            sA = fmaf(rowA[d], w, sA);
            sB = fmaf(rowB[d], w, sB);
        }
        qpA[e] = pk2(sA, sA);
        qpB[e] = pk2(sB, sB);
    }
    __syncthreads();

    const ulonglong2* K0 = (const ulonglong2*)sK[h][0];
    const ulonglong2* K1 = (const ulonglong2*)sK[h][1];
    const ulonglong2* K2 = (const ulonglong2*)sK[h][2];
    const ulonglong2* K3 = (const ulonglong2*)sK[h][3];
    const ulonglong2* V0 = (const ulonglong2*)sV[h][0];
    const ulonglong2* V1 = (const ulonglong2*)sV[h][1];
    const ulonglong2* V2 = (const ulonglong2*)sV[h][2];
    const ulonglong2* V3 = (const ulonglong2*)sV[h][3];

    u64t zero = pk2(0.0f, 0.0f);
    u64t sAp = zero, sBp = zero;
    u64t oA0 = zero, oA1 = zero, oA2 = zero, oA3 = zero;
    u64t oB0 = zero, oB1 = zero, oB2 = zero, oB3 = zero;
#pragma unroll
    for (int jg = 0; jg < 16; jg++) {
        ulonglong2 k0 = K0[jg], k1 = K1[jg], k2 = K2[jg], k3 = K3[jg];
        // row A dots
        u64t dA01 = mul2(qpA[0], k0.x);
        dA01 = fma2(qpA[1], k1.x, dA01);
        dA01 = fma2(qpA[2], k2.x, dA01);
        dA01 = fma2(qpA[3], k3.x, dA01);
        u64t dA23 = mul2(qpA[0], k0.y);
        dA23 = fma2(qpA[1], k1.y, dA23);
        dA23 = fma2(qpA[2], k2.y, dA23);
        dA23 = fma2(qpA[3], k3.y, dA23);
        // row B dots
        u64t dB01 = mul2(qpB[0], k0.x);
        dB01 = fma2(qpB[1], k1.x, dB01);
        dB01 = fma2(qpB[2], k2.x, dB01);
        dB01 = fma2(qpB[3], k3.x, dB01);
        u64t dB23 = mul2(qpB[0], k0.y);
        dB23 = fma2(qpB[1], k1.y, dB23);
        dB23 = fma2(qpB[2], k2.y, dB23);
        dB23 = fma2(qpB[3], k3.y, dB23);
        float xa0, xa1, xa2, xa3, xb0, xb1, xb2, xb3;
        up2(dA01, xa0, xa1); up2(dA23, xa2, xa3);
        up2(dB01, xb0, xb1); up2(dB23, xb2, xb3);
        u64t eA01 = pk2(ex2f(xa0), ex2f(xa1));
        u64t eA23 = pk2(ex2f(xa2), ex2f(xa3));
        u64t eB01 = pk2(ex2f(xb0), ex2f(xb1));
        u64t eB23 = pk2(ex2f(xb2), ex2f(xb3));
        sAp = add2(add2(sAp, eA01), eA23);
        sBp = add2(add2(sBp, eB01), eB23);
        ulonglong2 v0 = V0[jg], v1 = V1[jg], v2 = V2[jg], v3 = V3[jg];
        oA0 = fma2(eA01, v0.x, oA0); oA0 = fma2(eA23, v0.y, oA0);
        oA1 = fma2(eA01, v1.x, oA1); oA1 = fma2(eA23, v1.y, oA1);
        oA2 = fma2(eA01, v2.x, oA2); oA2 = fma2(eA23, v2.y, oA2);
        oA3 = fma2(eA01, v3.x, oA3); oA3 = fma2(eA23, v3.y, oA3);
        oB0 = fma2(eB01, v0.x, oB0); oB0 = fma2(eB23, v0.y, oB0);
        oB1 = fma2(eB01, v1.x, oB1); oB1 = fma2(eB23, v1.y, oB1);
        oB2 = fma2(eB01, v2.x, oB2); oB2 = fma2(eB23, v2.y, oB2);
        oB3 = fma2(eB01, v3.x, oB3); oB3 = fma2(eB23, v3.y, oB3);
    }

    float ua, ub, oeA[4], oeB[4];
    up2(sAp, ua, ub);
    float invA = 1.0f / (ua + ub);
    up2(sBp, ua, ub);
    float invB = 1.0f / (ua + ub);
    up2(oA0, ua, ub); oeA[0] = (ua + ub) * invA;
    up2(oA1, ua, ub); oeA[1] = (ua + ub) * invA;
    up2(oA2, ua, ub); oeA[2] = (ua + ub) * invA;
    up2(oA3, ua, ub); oeA[3] = (ua + ub) * invA;
    up2(oB0, ua, ub); oeB[0] = (ua + ub) * invB;
    up2(oB1, ua, ub); oeB[1] = (ua + ub) * invB;
    up2(oB2, ua, ub); oeB[2] = (ua + ub) * invB;
    up2(oB3, ua, ub); oeB[3] = (ua + ub) * invB;

    // partial output projection for this head -> sPart
#pragma unroll
    for (int d = 0; d < 8; d++) {
        float w0 = sWo[(h * 4 + 0) * 8 + d];
        float w1 = sWo[(h * 4 + 1) * 8 + d];
        float w2 = sWo[(h * 4 + 2) * 8 + d];
        float w3 = sWo[(h * 4 + 3) * 8 + d];
        sPart[h][d][i0]      = oeA[0]*w0 + oeA[1]*w1 + oeA[2]*w2 + oeA[3]*w3;
        sPart[h][d][i0 + 32] = oeB[0]*w0 + oeB[1]*w1 + oeB[2]*w2 + oeB[3]*w3;
    }
    __syncthreads();

    // final: 128 threads, (row, dhalf) = (tid>>1, tid&1)
    {
        const int row = tid >> 1;
        const int dh  = (tid & 1) * 4;
        float o0 = sbo[dh+0], o1 = sbo[dh+1], o2 = sbo[dh+2], o3 = sbo[dh+3];
#pragma unroll
        for (int hh = 0; hh < 4; hh++) {
            o0 += sPart[hh][dh+0][row];
            o1 += sPart[hh][dh+1][row];
            o2 += sPart[hh][dh+2][row];
            o3 += sPart[hh][dh+3][row];
        }
        float* zo = zout + (base + (long)row * stride) * 8 + dh;
        if (accum) {
            float4 prev = *(float4*)zo;
            o0 += prev.x; o1 += prev.y; o2 += prev.z; o3 += prev.w;
        }
        *(float4*)zo = make_float4(o0, o1, o2, o3);
    }
}

// ---------------------------------------------------------------------------
// Axial attention, L=20 (sequence axis; fixed geometry: inner=4096,
// outer_mult=81920, stride=4096). 256 threads = 2 seqs x 4 heads x 32 lanes,
// lane i<20 active. Warp-aligned broadcasts; one head per thread.
// EMBED=1: layer 0 — compute emb from x on the fly and persist to g_xt.
// ---------------------------------------------------------------------------
template<int EMBED>
__global__ void __launch_bounds__(256, 4)
axial_attn20(const float* __restrict__ zin, float* __restrict__ zout,
             const float* __restrict__ Wq, const float* __restrict__ Wkv,
             const float* __restrict__ Wo, const float* __restrict__ bo,
             const float* __restrict__ x, const float* __restrict__ conv_w,
             const float* __restrict__ pos_s, const float* __restrict__ pos_h,
             const float* __restrict__ pos_w)
{
    __shared__ float  sWq[128];        // pre-scaled
    __shared__ float2 sKV2[8][16];
    __shared__ float  sWo[128];
    __shared__ float  sbo[8];
    __shared__ __align__(16) float sK[2][4][4][20];
    __shared__ __align__(16) float sV[2][4][4][20];
    __shared__ float  sPart[2][4][8][20];
    __shared__ float  sCv[8];
    __shared__ float  sPS[160];
    __shared__ float  sPH[2][8];
    __shared__ float  sPW[2][8];

    const int tid = threadIdx.x;       // 0..255
    const int sl  = tid >> 7;          // seq slot
    const int h   = (tid >> 5) & 3;    // head
    const int i   = tid & 31;          // row lane (active if < 20)
    const bool active = (i < 20);

    if (tid < 128) sWq[tid] = Wq[tid] * QSCALE;
    if (tid < 128) {
        int d = tid >> 4, c = tid & 15;
        sKV2[d][c] = make_float2(Wkv[d * 32 + c], Wkv[d * 32 + 16 + c]);
    }
    if (tid < 128) sWo[tid] = Wo[tid];
    if (tid < 8) sbo[tid] = bo[tid];

    if (EMBED) {
        if (tid < 8) sCv[tid] = conv_w[tid];
        if (tid >= 64 && tid < 224) sPS[tid - 64] = pos_s[tid - 64];
        if (tid >= 224 && tid < 256) {
            int t2   = tid - 224;          // 0..31
            int slot = t2 >> 4;            // 0/1
            int idx  = t2 & 15;
            int d2   = idx & 7;
            int hwT  = (blockIdx.x * 2 + slot) & 4095;
            if (idx < 8) sPH[slot][d2] = pos_h[d2 * 64 + (hwT >> 6)];
            else         sPW[slot][d2] = pos_w[d2 * 64 + (hwT & 63)];
        }
        if (blockIdx.x == 0 && tid < Bb) g_logits[tid] = 0.0f;
    }

    const int seq = blockIdx.x * 2 + sl;
    const int b   = seq >> 12;          // / 4096
    const int hw  = seq & 4095;
    const long base = (long)b * 81920 + hw;

    __syncthreads();   // weights + embed tables ready

    float row[8];
    if (active) {
        if (EMBED) {
            float xv = x[((long)(b * Ss + i) << 12) + hw];
#pragma unroll
            for (int d = 0; d < 8; d++) {
                float v = fmaxf(xv * sCv[d], 0.0f);
                row[d] = v + sPS[i * 8 + d] + sPH[sl][d] + sPW[sl][d];
            }
            if (h == 0) {
                float* xo = g_xt + (base + (long)i * 4096) * 8;
                ((float4*)xo)[0] = make_float4(row[0], row[1], row[2], row[3]);
                ((float4*)xo)[1] = make_float4(row[4], row[5], row[6], row[7]);
            }
        } else {
            const float* zr = zin + (base + (long)i * 4096) * 8;
            float4 a0 = *(const float4*)zr;
            float4 a1 = *(const float4*)(zr + 4);
            row[0]=a0.x; row[1]=a0.y; row[2]=a0.z; row[3]=a0.w;
            row[4]=a1.x; row[5]=a1.y; row[6]=a1.z; row[7]=a1.w;
        }
    }

    u64t qp[4];
    if (active) {
        const u64t* kvw = (const u64t*)&sKV2[0][0];
#pragma unroll
        for (int e = 0; e < 4; e++) {
            u64t acc = mul2(pk2(row[0], row[0]), kvw[0 * 16 + h * 4 + e]);
#pragma unroll
            for (int d = 1; d < 8; d++)
                acc = fma2(pk2(row[d], row[d]), kvw[d * 16 + h * 4 + e], acc);
            float sk, sv;
            up2(acc, sk, sv);
            sK[sl][h][e][i] = sk;
            sV[sl][h][e][i] = sv;
        }
#pragma unroll
        for (int e = 0; e < 4; e++) {
            float s = 0.0f;
#pragma unroll
            for (int d = 0; d < 8; d++) s = fmaf(row[d], sWq[d * 16 + h * 4 + e], s);
            qp[e] = pk2(s, s);
        }
    }
    __syncthreads();

    if (active) {
        const ulonglong2* K0 = (const ulonglong2*)sK[sl][h][0];
        const ulonglong2* K1 = (const ulonglong2*)sK[sl][h][1];
        const ulonglong2* K2 = (const ulonglong2*)sK[sl][h][2];
        const ulonglong2* K3 = (const ulonglong2*)sK[sl][h][3];
        const ulonglong2* V0 = (const ulonglong2*)sV[sl][h][0];
        const ulonglong2* V1 = (const ulonglong2*)sV[sl][h][1];
        const ulonglong2* V2 = (const ulonglong2*)sV[sl][h][2];
        const ulonglong2* V3 = (const ulonglong2*)sV[sl][h][3];

        u64t zero = pk2(0.0f, 0.0f);
        u64t s01 = zero, o0 = zero, o1 = zero, o2 = zero, o3 = zero;
#pragma unroll
        for (int jg = 0; jg < 5; jg++) {
            ulonglong2 k0 = K0[jg], k1 = K1[jg], k2 = K2[jg], k3 = K3[jg];
            u64t d01 = mul2(qp[0], k0.x);
            d01 = fma2(qp[1], k1.x, d01);
            d01 = fma2(qp[2], k2.x, d01);
            d01 = fma2(qp[3], k3.x, d01);
            u64t d23 = mul2(qp[0], k0.y);
            d23 = fma2(qp[1], k1.y, d23);
            d23 = fma2(qp[2], k2.y, d23);
            d23 = fma2(qp[3], k3.y, d23);
            float x0, x1, x2, x3;
            up2(d01, x0, x1);
            up2(d23, x2, x3);
            u64t e01 = pk2(ex2f(x0), ex2f(x1));
            u64t e23 = pk2(ex2f(x2), ex2f(x3));
            s01 = add2(add2(s01, e01), e23);
            ulonglong2 v0 = V0[jg], v1 = V1[jg], v2 = V2[jg], v3 = V3[jg];
            o0 = fma2(e01, v0.x, o0); o0 = fma2(e23, v0.y, o0);
            o1 = fma2(e01, v1.x, o1); o1 = fma2(e23, v1.y, o1);
            o2 = fma2(e01, v2.x, o2); o2 = fma2(e23, v2.y, o2);
            o3 = fma2(e01, v3.x, o3); o3 = fma2(e23, v3.y, o3);
        }
        float sa, sb;
        up2(s01, sa, sb);
        float inv = 1.0f / (sa + sb);
        float oe[4];
        {
            float ua, ub;
            up2(o0, ua, ub); oe[0] = (ua + ub) * inv;
            up2(o1, ua, ub); oe[1] = (ua + ub) * inv;
            up2(o2, ua, ub); oe[2] = (ua + ub) * inv;
            up2(o3, ua, ub); oe[3] = (ua + ub) * inv;
        }
#pragma unroll
        for (int d = 0; d < 8; d++) {
            sPart[sl][h][d][i] = oe[0] * sWo[(h * 4 + 0) * 8 + d]
                               + oe[1] * sWo[(h * 4 + 1) * 8 + d]
                               + oe[2] * sWo[(h * 4 + 2) * 8 + d]
                               + oe[3] * sWo[(h * 4 + 3) * 8 + d];
        }
    }
    __syncthreads();

    // final: 80 tasks: (slot, row, dhalf)
    if (tid < 80) {
        const int sl2 = tid / 40;
        const int r2  = tid - sl2 * 40;
        const int row2 = r2 >> 1;
        const int dh   = (r2 & 1) * 4;
        const int seq2 = blockIdx.x * 2 + sl2;
        const int b2   = seq2 >> 12;
        const int hw2  = seq2 & 4095;
        const long base2 = (long)b2 * 81920 + hw2;

        float o0 = sbo[dh+0], o1 = sbo[dh+1], o2 = sbo[dh+2], o3 = sbo[dh+3];
#pragma unroll
        for (int hh = 0; hh < 4; hh++) {
            o0 += sPart[sl2][hh][dh+0][row2];
            o1 += sPart[sl2][hh][dh+1][row2];
            o2 += sPart[sl2][hh][dh+2][row2];
            o3 += sPart[sl2][hh][dh+3][row2];
        }
        float* zo = zout + (base2 + (long)row2 * 4096) * 8 + dh;
        *(float4*)zo = make_float4(o0, o1, o2, o3);
    }
}

// ---------------------------------------------------------------------------
// Epilogue
// ---------------------------------------------------------------------------
__global__ void reduce_kernel(const float* __restrict__ zfin,
                              const float* __restrict__ Wc)
{
    const int b = blockIdx.y;
    const int t = blockIdx.x * blockDim.x + threadIdx.x;
    const int d  = t & 7;
    const int hw = t >> 3;
    long base = (long)b * Ss * 32768 + (long)hw * 8 + d;
    float m = -1e30f;
#pragma unroll
    for (int s = 0; s < Ss; s++) {
        long o = base + (long)s * 32768;
        m = fmaxf(m, zfin[o] + g_xt[o]);
    }
    float val = m * Wc[d * 4096 + hw];

    __shared__ float red[256];
    red[threadIdx.x] = val;
    __syncthreads();
    for (int off = 128; off > 0; off >>= 1) {
        if (threadIdx.x < off) red[threadIdx.x] += red[threadIdx.x + off];
        __syncthreads();
    }
    if (threadIdx.x == 0) atomicAdd(&g_logits[b], red[0]);
}

__global__ void final_kernel(const float* __restrict__ bc, float* __restrict__ out)
{
    int b = threadIdx.x;
    if (b < Bb) {
        float lg = g_logits[b] + bc[0];
        out[b] = 1.0f / (1.0f + __expf(-lg));
    }
}

// ---------------------------------------------------------------------------
extern "C" void kernel_launch(void* const* d_in, const int* in_sizes, int n_in,
                              void* d_out, int out_size)
{
    const float* x      = (const float*)d_in[0];
    const float* conv_w = (const float*)d_in[1];
    const float* pos_s  = (const float*)d_in[2];
    const float* pos_h  = (const float*)d_in[3];
    const float* pos_w  = (const float*)d_in[4];
    const float* Wq     = (const float*)d_in[5];
    const float* Wkv    = (const float*)d_in[6];
    const float* Wo     = (const float*)d_in[7];
    const float* bo     = (const float*)d_in[8];
    const float* Wc     = (const float*)d_in[9];
    const float* bc     = (const float*)d_in[10];
    float* out = (float*)d_out;

    float *pXt = nullptr, *pA = nullptr, *pB = nullptr;
    cudaGetSymbolAddress((void**)&pXt, g_xt);
    cudaGetSymbolAddress((void**)&pA,  g_bufA);
    cudaGetSymbolAddress((void**)&pB,  g_bufB);

    float* cur = pXt;
    for (int l = 0; l < NLl; l++) {
        float* nxt = (l & 1) ? pB : pA;
        const float* wq0 = Wq  + (l * 3 + 0) * 128;
        const float* wk0 = Wkv + (l * 3 + 0) * 256;
        const float* wo0 = Wo  + (l * 3 + 0) * 128;
        const float* bo0 = bo  + (l * 3 + 0) * 8;

        // axis 1 (S, L=20): writes nxt; layer 0 fuses the embedding
        if (l == 0) {
            axial_attn20<1><<<Bb * IMm * IMm / 2, 256>>>(
                nullptr, nxt, wq0, wk0, wo0, bo0,
                x, conv_w, pos_s, pos_h, pos_w);
        } else {
            axial_attn20<0><<<Bb * IMm * IMm / 2, 256>>>(
                cur, nxt, wq0, wk0, wo0, bo0,
                nullptr, nullptr, nullptr, nullptr, nullptr);
        }
        // axis 2 (H, L=64): accumulate
        axial_attn64<<<Bb * Ss * IMm, 128>>>(
            cur, nxt, wq0 + 128, wk0 + 256, wo0 + 128, bo0 + 8,
            IMm, IMm * IMm, IMm, 1);
        // axis 3 (W, L=64): accumulate
        axial_attn64<<<Bb * Ss * IMm, 128>>>(
            cur, nxt, wq0 + 256, wk0 + 512, wo0 + 256, bo0 + 16,
            1, IMm, 1, 1);
        cur = nxt;
    }

    {
        dim3 grid(IMm * IMm * Dd / 256, Bb);
        reduce_kernel<<<grid, 256>>>(cur, Wc);
    }
    final_kernel<<<1, 32>>>(bc, out);
}